// round 5
// baseline (speedup 1.0000x reference)
#include <cuda_runtime.h>

#define TT   1024
#define BB   16
#define CC   1024
#define HH   16
#define KW   7
#define PADL 6
#define MM   (TT * BB)       // 16384
#define NN   (HH * KW)       // 112
#define KD   1024

#define BM 128
#define BK 32
#define GEMM_BLOCKS (MM / BM)              // 128
#define FILL_BLOCKS 2048
#define DENSE_F4    ((size_t)BB * HH * TT * TT / 4)   // 67108864

#define ASTR 130      // floats per p-row of A tile (even -> aligned LDS64)
#define BSTR 33       // ulls per o-row of B tile (odd -> conflict-free LDS64)

// softmaxed conv weights, [m = t*16+b][o = h*7+k]
__device__ float g_wsm[(size_t)MM * NN];

typedef unsigned long long ull;
__device__ __forceinline__ ull pk2(float lo, float hi) {
    ull r; asm("mov.b64 %0,{%1,%2};" : "=l"(r) : "f"(lo), "f"(hi)); return r;
}
__device__ __forceinline__ void upk2(ull v, float& lo, float& hi) {
    asm("mov.b64 {%0,%1},%2;" : "=f"(lo), "=f"(hi) : "l"(v));
}
__device__ __forceinline__ void fma2(ull& d, ull a, ull b) {
    asm("fma.rn.f32x2 %0,%1,%2,%3;" : "=l"(d) : "l"(a), "l"(b), "l"(d));
}

__global__ void knop() {}

// ---------------------------------------------------------------------------
// Fused kernel:
//   blockIdx % 17 == 0 : GEMM w = x@W^T + masked softmax -> g_wsm  (128 blocks)
//   else               : zero-fill slice of dense                  (2048 blocks)
// GEMM: BM=128, 8 rows/thread. A k-major (broadcast LDS64 pairs, f32x2-ready),
// B pre-duplicated ull stride 33 (single-phase conflict-free LDS64).
// ---------------------------------------------------------------------------
__global__ __launch_bounds__(256)
void k_fused(const float* __restrict__ x,
             const float* __restrict__ W,
             float* __restrict__ dense)
{
    if (blockIdx.x % 17u != 0u) {
        // ---- zero-fill branch: contiguous 512 KB per block ----
        int zid = blockIdx.x - blockIdx.x / 17u - 1;
        const int per = (int)(DENSE_F4 / FILL_BLOCKS);   // 32768 f4
        float4* d4 = (float4*)dense + (size_t)zid * per;
        float4 z = make_float4(0.f, 0.f, 0.f, 0.f);
#pragma unroll 4
        for (int i = threadIdx.x; i < per; i += 256)
            __stcs(d4 + i, z);
        return;
    }

    const int gid = blockIdx.x / 17u;          // 0..127

    __shared__ __align__(16) float Asf[BK * ASTR];   // 16640 B, Asf[p][m]
    __shared__ __align__(16) ull   Bsd[NN * BSTR];   // 29568 B, Bsd[o][p] dup'd

    const int tid   = threadIdx.x;
    const int tx    = tid & 15;     // head
    const int ty    = tid >> 4;     // row group: 8 rows
    const int mBase = gid * BM;

    const int kk  = tid & 31;       // loader: k within tile
    const int ldr = tid >> 5;       // loader: row phase 0..7

    ull acc[7][4];                  // [k-tap j][row-pair]
#pragma unroll
    for (int j = 0; j < 7; j++)
#pragma unroll
        for (int r = 0; r < 4; r++) acc[j][r] = 0ull;

    for (int k0 = 0; k0 < KD; k0 += BK) {
        // A tile 128x32 -> k-major. gmem coalesced; STS 2-way conflict (ok).
#pragma unroll
        for (int rr = 0; rr < 16; rr++) {
            int r = ldr + rr * 8;
            Asf[kk * ASTR + r] = x[(size_t)(mBase + r) * KD + k0 + kk];
        }
        // B tile 112x32, value duplicated into both f32x2 lanes.
#pragma unroll
        for (int oo = 0; oo < 14; oo++) {
            int o = ldr + oo * 8;
            float w = W[(size_t)o * KD + k0 + kk];
            Bsd[o * BSTR + kk] = pk2(w, w);
        }
        __syncthreads();

#pragma unroll 4
        for (int p = 0; p < BK; p++) {
            const float* ap = &Asf[p * ASTR + 8 * ty];
            ull a0 = *(const ull*)(ap + 0);
            ull a1 = *(const ull*)(ap + 2);
            ull a2 = *(const ull*)(ap + 4);
            ull a3 = *(const ull*)(ap + 6);
#pragma unroll
            for (int j = 0; j < 7; j++) {
                ull bb = Bsd[(tx * 7 + j) * BSTR + p];
                fma2(acc[j][0], a0, bb);
                fma2(acc[j][1], a1, bb);
                fma2(acc[j][2], a2, bb);
                fma2(acc[j][3], a3, bb);
            }
        }
        __syncthreads();
    }

    // ---- masked softmax over K=7 for this thread's 8 rows, head tx ----
#pragma unroll
    for (int rp = 0; rp < 4; rp++) {
        float f0[7], f1[7];
#pragma unroll
        for (int j = 0; j < 7; j++) upk2(acc[j][rp], f0[j], f1[j]);

#pragma unroll
        for (int half = 0; half < 2; half++) {
            float* f = half ? f1 : f0;
            int m = mBase + ty * 8 + rp * 2 + half;
            int t = m >> 4;
            int kmin = PADL - t; if (kmin < 0) kmin = 0;

            float mx = -1e30f;
#pragma unroll
            for (int k = 0; k < 7; k++)
                if (k >= kmin && f[k] > mx) mx = f[k];

            float e[7], s = 0.f;
#pragma unroll
            for (int k = 0; k < 7; k++) {
                e[k] = (k >= kmin) ? __expf(f[k] - mx) : 0.f;
                s += e[k];
            }
            float inv = 1.f / s;
            float* gp = &g_wsm[(size_t)m * NN + tx * 7];
#pragma unroll
            for (int k = 0; k < 7; k++)
                gp[k] = e[k] * inv;
        }
    }
}

// ---------------------------------------------------------------------------
// k2: two consecutive t per block; rows share 6 of their 7 gather rows.
//   out[t,b,:] = sum_k wsm[t,b,h,k] * x[clamp(t-6+k), b, :]
//   + band scatter into (already zeroed) dense
// ---------------------------------------------------------------------------
__global__ __launch_bounds__(256)
void k2_out_band(const float* __restrict__ x,
                 float* __restrict__ out,
                 float* __restrict__ dense)
{
    const int t0  = blockIdx.x * 2;
    const int b   = blockIdx.y;
    const int tid = threadIdx.x;

    __shared__ float sw[2 * NN];
    if (tid < 2 * NN) {
        int row = tid / NN, idx = tid - row * NN;
        sw[tid] = g_wsm[(size_t)((t0 + row) * BB + b) * NN + idx];
    }
    __syncthreads();

    const int h = tid >> 4;
    const float4* x4 = (const float4*)x;

    float4 v[8];
#pragma unroll
    for (int k = 0; k < 8; k++) {
        int pos = t0 - PADL + k;
        if (pos < 0) pos = 0;               // weight is exactly 0 there
        v[k] = x4[((size_t)(pos * BB + b) << 8) + tid];
    }

    const float* w0 = &sw[h * 7];
    const float* w1 = &sw[NN + h * 7];
    float4 a0 = make_float4(0.f, 0.f, 0.f, 0.f);
    float4 a1 = make_float4(0.f, 0.f, 0.f, 0.f);
#pragma unroll
    for (int k = 0; k < 7; k++) {
        float wk0 = w0[k], wk1 = w1[k];
        a0.x += wk0 * v[k].x;     a1.x += wk1 * v[k + 1].x;
        a0.y += wk0 * v[k].y;     a1.y += wk1 * v[k + 1].y;
        a0.z += wk0 * v[k].z;     a1.z += wk1 * v[k + 1].z;
        a0.w += wk0 * v[k].w;     a1.w += wk1 * v[k + 1].w;
    }
    float4* out4 = (float4*)out;
    out4[((size_t)(t0 * BB + b) << 8) + tid] = a0;
    out4[((size_t)((t0 + 1) * BB + b) << 8) + tid] = a1;

    // band scatter
    if (tid < 2 * NN) {
        int row = tid / NN, idx = tid - row * NN;
        int hh  = idx / 7;
        int k   = idx - hh * 7;
        int t   = t0 + row;
        int col = t - PADL + k;
        if (col >= 0)
            dense[((size_t)(b * HH + hh) << 20) + ((size_t)t << 10) + col] = sw[tid];
    }
}

// ---------------------------------------------------------------------------
extern "C" void kernel_launch(void* const* d_in, const int* in_sizes, int n_in,
                              void* d_out, int out_size)
{
    const float* x = (const float*)d_in[0];   // (T, B, C) fp32
    const float* W = (const float*)d_in[1];   // (H*K, C)  fp32
    float* out   = (float*)d_out;             // first T*B*C floats
    float* dense = out + (size_t)MM * CC;     // then (B*H, T, T)

    // 4 launches/call so ncu (-s 5) profiles the fused kernel next round.
    knop<<<1, 32>>>();
    k_fused<<<GEMM_BLOCKS + FILL_BLOCKS, 256>>>(x, W, dense);
    dim3 g2(TT / 2, BB);
    k2_out_band<<<g2, 256>>>(x, out, dense);
    knop<<<1, 32>>>();
}

// round 6
// speedup vs baseline: 1.0183x; 1.0183x over previous
#include <cuda_runtime.h>

#define TT   1024
#define BB   16
#define CC   1024
#define HH   16
#define KW   7
#define PADL 6
#define MM   (TT * BB)       // 16384
#define NN   (HH * KW)       // 112
#define KD   1024

#define BM 128
#define BK 32
#define GEMM_BLOCKS (MM / BM)              // 128
#define FILL_BLOCKS 2048
#define FILL_BYTES  (512 * 1024)           // per fill block (x16 chunks of 32KB)

#define ASTR 130      // floats per p-row of A tile
#define BSTR 33       // ulls per o-row of B tile (14*tx mod 32 covers all banks)

// softmaxed conv weights, [m = t*16+b][o = h*7+k]
__device__ float g_wsm[(size_t)MM * NN];

typedef unsigned long long ull;
__device__ __forceinline__ ull pk2(float lo, float hi) {
    ull r; asm("mov.b64 %0,{%1,%2};" : "=l"(r) : "f"(lo), "f"(hi)); return r;
}
__device__ __forceinline__ void upk2(ull v, float& lo, float& hi) {
    asm("mov.b64 {%0,%1},%2;" : "=f"(lo), "=f"(hi) : "l"(v));
}
__device__ __forceinline__ void fma2(ull& d, ull a, ull b) {
    asm("fma.rn.f32x2 %0,%1,%2,%3;" : "=l"(d) : "l"(a), "l"(b), "l"(d));
}
__device__ __forceinline__ unsigned smem_u32(const void* p) {
    unsigned a;
    asm("{ .reg .u64 t; cvta.to.shared.u64 t, %1; cvt.u32.u64 %0, t; }"
        : "=r"(a) : "l"(p));
    return a;
}

// ---------------------------------------------------------------------------
// K1 fused:
//   blockIdx % 17 == 0 : GEMM w = x@W^T + masked softmax -> g_wsm (128 blocks)
//   else               : TMA bulk-store zero-fill of dense        (2048 blocks)
// The fill path issues cp.async.bulk (SMEM->GMEM) so it rides the TMA engine,
// not the LSU; the GEMM rides FMA + shared. Disjoint pipes -> real overlap.
// ---------------------------------------------------------------------------
__global__ __launch_bounds__(256)
void k1_fused(const float* __restrict__ x,
              const float* __restrict__ W,
              float* __restrict__ dense)
{
    __shared__ __align__(128) char sm[46208];    // GEMM tiles / fill zero-buf overlay
    const int tid = threadIdx.x;

    if (blockIdx.x % 17u != 0u) {
        // ---- TMA zero-fill branch: 512 KB contiguous per block ----
        int zid = blockIdx.x - blockIdx.x / 17u - 1;         // 0..2047

        float4* z4 = (float4*)sm;                             // 32 KB zero image
#pragma unroll
        for (int i = tid; i < 2048; i += 256)
            z4[i] = make_float4(0.f, 0.f, 0.f, 0.f);
        __syncthreads();
        asm volatile("fence.proxy.async.shared::cta;" ::: "memory");

        if (tid == 0) {
            unsigned saddr = smem_u32(sm);
            char* g = (char*)dense + (size_t)zid * FILL_BYTES;
#pragma unroll
            for (int c = 0; c < 16; c++) {
                asm volatile(
                    "cp.async.bulk.global.shared::cta.bulk_group [%0], [%1], %2;"
                    :: "l"(g + c * 32768), "r"(saddr), "r"(32768) : "memory");
            }
            asm volatile("cp.async.bulk.commit_group;" ::: "memory");
            asm volatile("cp.async.bulk.wait_group 0;" ::: "memory");
        }
        __syncthreads();
        return;
    }

    // ---- GEMM branch: BM=128, 8 rows/thread, f32x2 math ----
    float* Asf = (float*)sm;                       // [BK][ASTR]  16640 B
    ull*   Bsd = (ull*)(sm + 16640);               // [NN][BSTR]  29568 B

    const int gid   = blockIdx.x / 17u;            // 0..127
    const int tx    = tid & 15;                    // head
    const int ty    = tid >> 4;                    // 8-row group
    const int mBase = gid * BM;

    const int kk  = tid & 31;
    const int ldr = tid >> 5;

    ull acc[7][4];
#pragma unroll
    for (int j = 0; j < 7; j++)
#pragma unroll
        for (int r = 0; r < 4; r++) acc[j][r] = 0ull;

    for (int k0 = 0; k0 < KD; k0 += BK) {
#pragma unroll
        for (int rr = 0; rr < 16; rr++) {
            int r = ldr + rr * 8;
            Asf[kk * ASTR + r] = x[(size_t)(mBase + r) * KD + k0 + kk];
        }
#pragma unroll
        for (int oo = 0; oo < 14; oo++) {
            int o = ldr + oo * 8;
            float w = W[(size_t)o * KD + k0 + kk];
            Bsd[o * BSTR + kk] = pk2(w, w);
        }
        __syncthreads();

#pragma unroll 4
        for (int p = 0; p < BK; p++) {
            const float* ap = &Asf[p * ASTR + 8 * ty];
            ull a0 = *(const ull*)(ap + 0);
            ull a1 = *(const ull*)(ap + 2);
            ull a2 = *(const ull*)(ap + 4);
            ull a3 = *(const ull*)(ap + 6);
#pragma unroll
            for (int j = 0; j < 7; j++) {
                ull bb = Bsd[(tx * 7 + j) * BSTR + p];
                fma2(acc[j][0], a0, bb);
                fma2(acc[j][1], a1, bb);
                fma2(acc[j][2], a2, bb);
                fma2(acc[j][3], a3, bb);
            }
        }
        __syncthreads();
    }

    // masked softmax over K=7 for this thread's 8 rows, head tx
#pragma unroll
    for (int rp = 0; rp < 4; rp++) {
        float f0[7], f1[7];
#pragma unroll
        for (int j = 0; j < 7; j++) upk2(acc[j][rp], f0[j], f1[j]);

#pragma unroll
        for (int half = 0; half < 2; half++) {
            float* f = half ? f1 : f0;
            int m = mBase + ty * 8 + rp * 2 + half;
            int t = m >> 4;
            int kmin = PADL - t; if (kmin < 0) kmin = 0;

            float mx = -1e30f;
#pragma unroll
            for (int k = 0; k < 7; k++)
                if (k >= kmin && f[k] > mx) mx = f[k];

            float e[7], s = 0.f;
#pragma unroll
            for (int k = 0; k < 7; k++) {
                e[k] = (k >= kmin) ? __expf(f[k] - mx) : 0.f;
                s += e[k];
            }
            float inv = 1.f / s;
            float* gp = &g_wsm[(size_t)m * NN + tx * 7];
#pragma unroll
            for (int k = 0; k < 7; k++)
                gp[k] = e[k] * inv;
        }
    }
}

// ---------------------------------------------------------------------------
// k2: FOUR consecutive t per block (rows share gather loads; 10 loads feed 4
// outputs).  out[t,b,:] = sum_k wsm[t,b,h,k] * x[clamp(t-6+k), b, :]
// + band scatter into the (already zeroed) dense.
// ---------------------------------------------------------------------------
__global__ __launch_bounds__(256)
void k2_out_band(const float* __restrict__ x,
                 float* __restrict__ out,
                 float* __restrict__ dense)
{
    const int t0  = blockIdx.x * 4;
    const int b   = blockIdx.y;
    const int tid = threadIdx.x;

    __shared__ float sw[4 * NN];
    for (int e = tid; e < 4 * NN; e += 256) {
        int r = e / NN, idx = e - r * NN;
        sw[e] = g_wsm[(size_t)((t0 + r) * BB + b) * NN + idx];
    }
    __syncthreads();

    const int h = tid >> 4;
    const float4* x4 = (const float4*)x;

    float4 v[10];
#pragma unroll
    for (int k = 0; k < 10; k++) {
        int pos = t0 - PADL + k;
        if (pos < 0) pos = 0;                 // weight is exactly 0 there
        v[k] = x4[((size_t)(pos * BB + b) << 8) + tid];
    }

    float4* out4 = (float4*)out;
#pragma unroll
    for (int r = 0; r < 4; r++) {
        const float* wr = &sw[r * NN + h * 7];
        float4 a = make_float4(0.f, 0.f, 0.f, 0.f);
#pragma unroll
        for (int k = 0; k < 7; k++) {
            float wk = wr[k];
            a.x += wk * v[r + k].x;
            a.y += wk * v[r + k].y;
            a.z += wk * v[r + k].z;
            a.w += wk * v[r + k].w;
        }
        out4[((size_t)((t0 + r) * BB + b) << 8) + tid] = a;
    }

    // band scatter: 4 rows x 112 entries
#pragma unroll
    for (int e = tid; e < 4 * NN; e += 256) {
        int r   = e / NN, idx = e - r * NN;
        int hh  = idx / 7;
        int k   = idx - hh * 7;
        int t   = t0 + r;
        int col = t - PADL + k;
        if (col >= 0)
            dense[((size_t)(b * HH + hh) << 20) + ((size_t)t << 10) + col] = sw[e];
    }
}

// ---------------------------------------------------------------------------
extern "C" void kernel_launch(void* const* d_in, const int* in_sizes, int n_in,
                              void* d_out, int out_size)
{
    const float* x = (const float*)d_in[0];   // (T, B, C) fp32
    const float* W = (const float*)d_in[1];   // (H*K, C)  fp32
    float* out   = (float*)d_out;             // first T*B*C floats
    float* dense = out + (size_t)MM * CC;     // then (B*H, T, T)

    k1_fused<<<GEMM_BLOCKS + FILL_BLOCKS, 256>>>(x, W, dense);

    dim3 g2(TT / 4, BB);
    k2_out_band<<<g2, 256>>>(x, out, dense);
}

// round 7
// speedup vs baseline: 1.4379x; 1.4121x over previous
#include <cuda_runtime.h>

#define TT   1024
#define BB   16
#define CC   1024
#define HH   16
#define KW   7
#define PADL 6
#define MM   (TT * BB)       // 16384
#define NN   (HH * KW)       // 112
#define KD   1024

#define BM 128
#define BK 32
#define GEMM_BLOCKS (MM / BM)                       // 128
#define DENSE_BYTES ((size_t)BB * HH * TT * TT * 4) // 1 GiB

#define ASTR 130      // floats per p-row of A tile
#define BSTR 33       // ulls per o-row of B tile

// softmaxed conv weights, [m = t*16+b][o = h*7+k]
__device__ float g_wsm[(size_t)MM * NN];

typedef unsigned long long ull;
__device__ __forceinline__ ull pk2(float lo, float hi) {
    ull r; asm("mov.b64 %0,{%1,%2};" : "=l"(r) : "f"(lo), "f"(hi)); return r;
}
__device__ __forceinline__ void upk2(ull v, float& lo, float& hi) {
    asm("mov.b64 {%0,%1},%2;" : "=f"(lo), "=f"(hi) : "l"(v));
}
__device__ __forceinline__ void fma2(ull& d, ull a, ull b) {
    asm("fma.rn.f32x2 %0,%1,%2,%3;" : "=l"(d) : "l"(a), "l"(b), "l"(d));
}

__global__ void knop() {}

// ---------------------------------------------------------------------------
// GEMM  w = x @ W^T (16384 x 112 x 1024) + masked softmax over K=7 -> g_wsm
// BM=128, 8 rows/thread, f32x2 math. A k-major (broadcast LDS64 pairs),
// B pre-duplicated ull stride 33 (conflict-free LDS64).
// ---------------------------------------------------------------------------
__global__ __launch_bounds__(256)
void k_gemm_softmax(const float* __restrict__ x,
                    const float* __restrict__ W)
{
    __shared__ __align__(16) float Asf[BK * ASTR];   // 16640 B
    __shared__ __align__(16) ull   Bsd[NN * BSTR];   // 29568 B

    const int tid   = threadIdx.x;
    const int tx    = tid & 15;     // head
    const int ty    = tid >> 4;     // 8-row group
    const int mBase = blockIdx.x * BM;

    const int kk  = tid & 31;
    const int ldr = tid >> 5;

    ull acc[7][4];
#pragma unroll
    for (int j = 0; j < 7; j++)
#pragma unroll
        for (int r = 0; r < 4; r++) acc[j][r] = 0ull;

    for (int k0 = 0; k0 < KD; k0 += BK) {
#pragma unroll
        for (int rr = 0; rr < 16; rr++) {
            int r = ldr + rr * 8;
            Asf[kk * ASTR + r] = x[(size_t)(mBase + r) * KD + k0 + kk];
        }
#pragma unroll
        for (int oo = 0; oo < 14; oo++) {
            int o = ldr + oo * 8;
            float w = W[(size_t)o * KD + k0 + kk];
            Bsd[o * BSTR + kk] = pk2(w, w);
        }
        __syncthreads();

#pragma unroll 4
        for (int p = 0; p < BK; p++) {
            const float* ap = &Asf[p * ASTR + 8 * ty];
            ull a0 = *(const ull*)(ap + 0);
            ull a1 = *(const ull*)(ap + 2);
            ull a2 = *(const ull*)(ap + 4);
            ull a3 = *(const ull*)(ap + 6);
#pragma unroll
            for (int j = 0; j < 7; j++) {
                ull bb = Bsd[(tx * 7 + j) * BSTR + p];
                fma2(acc[j][0], a0, bb);
                fma2(acc[j][1], a1, bb);
                fma2(acc[j][2], a2, bb);
                fma2(acc[j][3], a3, bb);
            }
        }
        __syncthreads();
    }

    // masked softmax over K=7 for this thread's 8 rows, head tx
#pragma unroll
    for (int rp = 0; rp < 4; rp++) {
        float f0[7], f1[7];
#pragma unroll
        for (int j = 0; j < 7; j++) upk2(acc[j][rp], f0[j], f1[j]);

#pragma unroll
        for (int half = 0; half < 2; half++) {
            float* f = half ? f1 : f0;
            int m = mBase + ty * 8 + rp * 2 + half;
            int t = m >> 4;
            int kmin = PADL - t; if (kmin < 0) kmin = 0;

            float mx = -1e30f;
#pragma unroll
            for (int k = 0; k < 7; k++)
                if (k >= kmin && f[k] > mx) mx = f[k];

            float e[7], s = 0.f;
#pragma unroll
            for (int k = 0; k < 7; k++) {
                e[k] = (k >= kmin) ? __expf(f[k] - mx) : 0.f;
                s += e[k];
            }
            float inv = 1.f / s;
            float* gp = &g_wsm[(size_t)m * NN + tx * 7];
#pragma unroll
            for (int k = 0; k < 7; k++)
                gp[k] = e[k] * inv;
        }
    }
}

// ---------------------------------------------------------------------------
// k2: four consecutive t per block; 10 gather loads feed 4 outputs.
//   out[t,b,:] = sum_k wsm[t,b,h,k] * x[clamp(t-6+k), b, :]
//   + band scatter into the (already zeroed) dense.
// ---------------------------------------------------------------------------
__global__ __launch_bounds__(256)
void k2_out_band(const float* __restrict__ x,
                 float* __restrict__ out,
                 float* __restrict__ dense)
{
    const int t0  = blockIdx.x * 4;
    const int b   = blockIdx.y;
    const int tid = threadIdx.x;

    __shared__ float sw[4 * NN];
    for (int e = tid; e < 4 * NN; e += 256) {
        int r = e / NN, idx = e - r * NN;
        sw[e] = g_wsm[(size_t)((t0 + r) * BB + b) * NN + idx];
    }
    __syncthreads();

    const int h = tid >> 4;
    const float4* x4 = (const float4*)x;

    float4 v[10];
#pragma unroll
    for (int k = 0; k < 10; k++) {
        int pos = t0 - PADL + k;
        if (pos < 0) pos = 0;                 // weight is exactly 0 there
        v[k] = x4[((size_t)(pos * BB + b) << 8) + tid];
    }

    float4* out4 = (float4*)out;
#pragma unroll
    for (int r = 0; r < 4; r++) {
        const float* wr = &sw[r * NN + h * 7];
        float4 a = make_float4(0.f, 0.f, 0.f, 0.f);
#pragma unroll
        for (int k = 0; k < 7; k++) {
            float wk = wr[k];
            a.x += wk * v[r + k].x;
            a.y += wk * v[r + k].y;
            a.z += wk * v[r + k].z;
            a.w += wk * v[r + k].w;
        }
        out4[((size_t)((t0 + r) * BB + b) << 8) + tid] = a;
    }

    // band scatter: 4 rows x 112 entries
#pragma unroll
    for (int e = tid; e < 4 * NN; e += 256) {
        int r   = e / NN, idx = e - r * NN;
        int hh  = idx / 7;
        int k   = idx - hh * 7;
        int t   = t0 + r;
        int col = t - PADL + k;
        if (col >= 0)
            dense[((size_t)(b * HH + hh) << 20) + ((size_t)t << 10) + col] = sw[e];
    }
}

// ---------------------------------------------------------------------------
// Launch order: knop, k_gemm_softmax, memset(dense), k2.
// 3 kernel launches/call => overall kernel-launch #7 = k_gemm_softmax,
// so ncu finally profiles the GEMM. Memset nodes are not kernel launches.
// ---------------------------------------------------------------------------
extern "C" void kernel_launch(void* const* d_in, const int* in_sizes, int n_in,
                              void* d_out, int out_size)
{
    const float* x = (const float*)d_in[0];   // (T, B, C) fp32
    const float* W = (const float*)d_in[1];   // (H*K, C)  fp32
    float* out   = (float*)d_out;             // first T*B*C floats
    float* dense = out + (size_t)MM * CC;     // then (B*H, T, T)

    knop<<<1, 32>>>();
    k_gemm_softmax<<<GEMM_BLOCKS, 256>>>(x, W);
    cudaMemsetAsync(dense, 0, DENSE_BYTES);
    dim3 g2(TT / 4, BB);
    k2_out_band<<<g2, 256>>>(x, out, dense);
}